// round 5
// baseline (speedup 1.0000x reference)
#include <cuda_runtime.h>
#include <cstdint>

// ---------------------------------------------------------------------------
// TripletFeatures: M=41, p=20.  Index set: |m*n|<=20, n>=m, |m|+|n|<=20, K=173.
// out[b,c,k] = Re( S_mn * E[p+n,c] ) + (m!=n) * Re( S_nm * E[p+m,c] )
//   with S_xy = sum_c E[p+x,c]*conj(E[p+x+y,c])
// Output contract (verified R3): float32 (B, 2, K), REAL PART ONLY.
// ---------------------------------------------------------------------------

struct Tab { int n; unsigned pk[224]; };

__host__ __device__ constexpr Tab make_tab() {
    Tab t{}; t.n = 0;
    for (int m = -20; m <= 20; ++m) {
        for (int n = -20; n <= 20; ++n) {
            int am = m < 0 ? -m : m;
            int an = n < 0 ? -n : n;
            if (am * an <= 20 && n >= m && am + an <= 20) {
                unsigned u = m + 20, v = n + 20, w = u + v - 20;
                t.pk[t.n] = u | (v << 8) | (w << 16);
                t.n = t.n + 1;
            }
        }
    }
    return t;
}

constexpr int K = make_tab().n;
static_assert(K == 173, "unexpected index-set size");

constexpr int WARPS = 8;         // warps per block
constexpr int BPW   = 4;         // batches per warp
constexpr int BPB   = WARPS * BPW;   // 32 batches per block
constexpr int NPOS  = 41;
constexpr int ME    = 82;        // floats per batch per input array
constexpr int KITER = (K + 31) / 32; // 6

__global__ void __launch_bounds__(WARPS * 32, 3)
triplet_kernel(const float* __restrict__ er,
               const float* __restrict__ ei,
               float* __restrict__ out,
               int B)
{
    static constexpr Tab TAB = make_tab();

    __shared__ float4   Esh[BPB][NPOS];   // (re0, im0, re1, im1) per position
    __shared__ unsigned tab_s[192];

    const int tid  = threadIdx.x;
    const int w    = tid >> 5;
    const int lane = tid & 31;
    const int bbase = blockIdx.x * BPB;

    for (int j = tid; j < K; j += WARPS * 32) tab_s[j] = TAB.pk[j];

    // Stage 32 batches: fully coalesced float2 reads, streaming (no reuse).
    {
        const float2* er2 = reinterpret_cast<const float2*>(er) + (size_t)bbase * NPOS;
        const float2* ei2 = reinterpret_cast<const float2*>(ei) + (size_t)bbase * NPOS;
        constexpr int TOT = BPB * NPOS;   // 1312
        for (int idx = tid; idx < TOT; idx += WARPS * 32) {
            const int bl = idx / NPOS;
            const int p  = idx - bl * NPOS;
            if (bbase + bl < B) {
                const float2 r  = __ldcs(&er2[idx]);
                const float2 im = __ldcs(&ei2[idx]);
                Esh[bl][p] = make_float4(r.x, im.x, r.y, im.y);
            }
        }
    }
    __syncthreads();

    const int wb = w * BPW;                       // local batch row base
    const long long gb = (long long)bbase + wb;   // global batch base
    float* ob = out + gb * (2 * K);

    #pragma unroll
    for (int i = 0; i < KITER; ++i) {
        const int k = lane + 32 * i;
        if (k < K) {
            const unsigned pk = tab_s[k];
            const int u  = pk & 0xff;
            const int v  = (pk >> 8) & 0xff;
            const int ww = (pk >> 16) & 0xff;
            const bool sym = (u != v);

            #pragma unroll
            for (int j = 0; j < BPW; ++j) {
                if (gb + j < B) {
                    const float4 U = Esh[wb + j][u];
                    const float4 V = Esh[wb + j][v];
                    const float4 W = Esh[wb + j][ww];

                    const float Sr = U.x * W.x + U.y * W.y + U.z * W.z + U.w * W.w;
                    const float Si = U.y * W.x - U.x * W.y + U.w * W.z - U.z * W.w;

                    float o0 = Sr * V.x - Si * V.y;
                    float o1 = Sr * V.z - Si * V.w;

                    if (sym) {
                        const float Tr = V.x * W.x + V.y * W.y + V.z * W.z + V.w * W.w;
                        const float Ti = V.y * W.x - V.x * W.y + V.w * W.z - V.z * W.w;
                        o0 += Tr * U.x - Ti * U.y;
                        o1 += Tr * U.z - Ti * U.w;
                    }

                    float* obj = ob + j * (2 * K);
                    __stcs(obj + k, o0);       // out[b+j, 0, k]
                    __stcs(obj + K + k, o1);   // out[b+j, 1, k]
                }
            }
        }
    }
}

extern "C" void kernel_launch(void* const* d_in, const int* in_sizes, int n_in,
                              void* d_out, int out_size)
{
    const float* er = (const float*)d_in[0];   // E_real (B, 41, 2) float32
    const float* ei = (const float*)d_in[1];   // E_imag (B, 41, 2) float32
    float* out = (float*)d_out;                // float32 (B, 2, K) real parts

    const int B = in_sizes[0] / ME;
    const int grid = (B + BPB - 1) / BPB;

    triplet_kernel<<<grid, WARPS * 32>>>(er, ei, out, B);
}